// round 1
// baseline (speedup 1.0000x reference)
#include <cuda_runtime.h>
#include <cuda_bf16.h>

#define NN 16384
#define DIM 32
#define OUTD 16
#define BN_EPS 1e-5f

// Scratch (allocation-free rule: __device__ globals)
__device__ float g_h1[(size_t)NN * DIM];   // pre-BN hidden (2 MB)
__device__ float g_stats[2 * DIM];         // [0:32) sum, [32:64) sumsq of h1 columns
__device__ float g_pool[DIM];              // pooled sum of h2 columns

// ---------------------------------------------------------------------------
// K0: zero the atomic accumulators (must run every graph replay)
// ---------------------------------------------------------------------------
__global__ void k_zero() {
    int t = threadIdx.x;
    if (t < 2 * DIM) g_stats[t] = 0.f;
    if (t < DIM)     g_pool[t]  = 0.f;
}

// ---------------------------------------------------------------------------
// K1: agg = adj^T @ x (streaming, sparsity-aware), fused h1 = (x+agg)@W1 + b1,
//     plus BN partial sums. Grid: 512 blocks (one per 32-column tile of adj),
//     256 threads (8 warps x 32 lanes). Warp w scans j in [w*2048, (w+1)*2048).
// ---------------------------------------------------------------------------
__global__ __launch_bounds__(256) void k_agg(
    const int*   __restrict__ adj,
    const float* __restrict__ x,
    const float* __restrict__ W1,
    const float* __restrict__ b1)
{
    const int tid  = threadIdx.x;
    const int w    = tid >> 5;
    const int lane = tid & 31;
    const int i0   = blockIdx.x * 32;
    const int i    = i0 + lane;               // adj column owned by this lane

    float acc[DIM];
    #pragma unroll
    for (int d = 0; d < DIM; d++) acc[d] = 0.f;

    const int jbeg = w * (NN / 8);
    const int* ap = adj + (size_t)jbeg * NN + i;

    // 2048 rows per warp, unroll 8 -> 8 outstanding 128B warp-loads
    for (int j = jbeg; j < jbeg + (NN / 8); j += 8) {
        int a[8];
        #pragma unroll
        for (int u = 0; u < 8; u++) a[u] = ap[(size_t)u * NN];
        ap += (size_t)8 * NN;

        int any = (a[0]|a[1]|a[2]|a[3]) | (a[4]|a[5]|a[6]|a[7]);
        if (__ballot_sync(0xFFFFFFFFu, any)) {        // ~6% taken
            #pragma unroll
            for (int u = 0; u < 8; u++) {
                if (__any_sync(0xFFFFFFFFu, a[u])) {
                    if (a[u]) {
                        float s = (float)a[u];
                        const float4* xr = (const float4*)(x + (size_t)(j + u) * DIM);
                        #pragma unroll
                        for (int q = 0; q < 8; q++) {
                            float4 v = xr[q];
                            acc[4*q+0] += s * v.x;
                            acc[4*q+1] += s * v.y;
                            acc[4*q+2] += s * v.z;
                            acc[4*q+3] += s * v.w;
                        }
                    }
                }
            }
        }
    }

    // Warp 0 folds in x[i] (the (1+eps)*x term, eps=0)
    if (w == 0) {
        const float4* xr = (const float4*)(x + (size_t)i * DIM);
        #pragma unroll
        for (int q = 0; q < 8; q++) {
            float4 v = xr[q];
            acc[4*q+0] += v.x; acc[4*q+1] += v.y;
            acc[4*q+2] += v.z; acc[4*q+3] += v.w;
        }
    }

    // Cross-warp reduction via padded shared (bank-conflict-free)
    __shared__ float red[8][32][33];
    #pragma unroll
    for (int d = 0; d < DIM; d++) red[w][lane][d] = acc[d];
    __syncthreads();

    // Fused first linear: node n = lane, outputs ob..ob+3 where ob = 4*w
    const int n  = lane;
    const int ob = w * 4;
    float o0 = b1[ob+0], o1 = b1[ob+1], o2 = b1[ob+2], o3 = b1[ob+3];
    #pragma unroll
    for (int d = 0; d < DIM; d++) {
        float v = red[0][n][d] + red[1][n][d] + red[2][n][d] + red[3][n][d]
                + red[4][n][d] + red[5][n][d] + red[6][n][d] + red[7][n][d];
        const float* wr = W1 + d * DIM + ob;   // warp-uniform
        o0 = fmaf(v, wr[0], o0);
        o1 = fmaf(v, wr[1], o1);
        o2 = fmaf(v, wr[2], o2);
        o3 = fmaf(v, wr[3], o3);
    }

    float4 hv = make_float4(o0, o1, o2, o3);
    *(float4*)(g_h1 + (size_t)(i0 + n) * DIM + ob) = hv;

    // BN partial sums: reduce across the 32 nodes (lanes) of this warp
    float s0 = o0, s1 = o1, s2 = o2, s3 = o3;
    float q0 = o0*o0, q1 = o1*o1, q2 = o2*o2, q3 = o3*o3;
    #pragma unroll
    for (int off = 16; off > 0; off >>= 1) {
        s0 += __shfl_down_sync(0xFFFFFFFFu, s0, off);
        s1 += __shfl_down_sync(0xFFFFFFFFu, s1, off);
        s2 += __shfl_down_sync(0xFFFFFFFFu, s2, off);
        s3 += __shfl_down_sync(0xFFFFFFFFu, s3, off);
        q0 += __shfl_down_sync(0xFFFFFFFFu, q0, off);
        q1 += __shfl_down_sync(0xFFFFFFFFu, q1, off);
        q2 += __shfl_down_sync(0xFFFFFFFFu, q2, off);
        q3 += __shfl_down_sync(0xFFFFFFFFu, q3, off);
    }
    if (lane == 0) {
        atomicAdd(&g_stats[ob+0], s0);  atomicAdd(&g_stats[ob+1], s1);
        atomicAdd(&g_stats[ob+2], s2);  atomicAdd(&g_stats[ob+3], s3);
        atomicAdd(&g_stats[DIM+ob+0], q0);  atomicAdd(&g_stats[DIM+ob+1], q1);
        atomicAdd(&g_stats[DIM+ob+2], q2);  atomicAdd(&g_stats[DIM+ob+3], q3);
    }
}

// ---------------------------------------------------------------------------
// K2: BN(train stats) + ReLU + @W2 + ReLU + mean-pool partials.
//     Grid: 64 blocks x 256 threads, one node per thread.
// ---------------------------------------------------------------------------
__global__ __launch_bounds__(256) void k_mlp2(
    const float* __restrict__ gamma,
    const float* __restrict__ beta,
    const float* __restrict__ W2,
    const float* __restrict__ b2)
{
    __shared__ float sh[256 * 33];       // padded h1 staging
    __shared__ float sW2T[DIM * DIM];    // W2 transposed: [o][d]
    __shared__ float sScale[DIM], sShift[DIM], sB2[DIM], sPool[DIM];

    const int tid  = threadIdx.x;
    const int base = blockIdx.x * 256;

    if (tid < DIM) {
        float mean = g_stats[tid] * (1.f / NN);
        float var  = g_stats[DIM + tid] * (1.f / NN) - mean * mean;
        float sc   = gamma[tid] * rsqrtf(var + BN_EPS);
        sScale[tid] = sc;
        sShift[tid] = beta[tid] - mean * sc;
        sB2[tid]    = b2[tid];
        sPool[tid]  = 0.f;
    }
    for (int k = tid; k < DIM * DIM; k += 256) {
        int d = k >> 5, o = k & 31;
        sW2T[o * DIM + d] = W2[k];
    }
    // Coalesced global reads, conflict-free padded shared writes
    const float* src = g_h1 + (size_t)base * DIM;
    for (int k = tid; k < 256 * DIM; k += 256)
        sh[(k >> 5) * 33 + (k & 31)] = src[k];
    __syncthreads();

    const float* hrow = sh + tid * 33;
    float v[DIM];
    #pragma unroll
    for (int d = 0; d < DIM; d++)
        v[d] = fmaxf(fmaf(hrow[d], sScale[d], sShift[d]), 0.f);

    const int lane = tid & 31;
    #pragma unroll
    for (int o = 0; o < DIM; o++) {
        float h2 = sB2[o];
        const float* wr = sW2T + o * DIM;    // warp-uniform, contiguous
        #pragma unroll
        for (int d = 0; d < DIM; d++) h2 = fmaf(v[d], wr[d], h2);
        h2 = fmaxf(h2, 0.f);
        // reduce across 32 nodes (lanes), then one shared atomic
        #pragma unroll
        for (int off = 16; off > 0; off >>= 1)
            h2 += __shfl_down_sync(0xFFFFFFFFu, h2, off);
        if (lane == 0) atomicAdd(&sPool[o], h2);
    }
    __syncthreads();
    if (tid < DIM) atomicAdd(&g_pool[tid], sPool[tid]);
}

// ---------------------------------------------------------------------------
// K3: out = (pool/N) @ Wf + bf   (1 x 16)
// ---------------------------------------------------------------------------
__global__ void k_final(const float* __restrict__ Wf,
                        const float* __restrict__ bf,
                        float* __restrict__ out)
{
    int o = threadIdx.x;
    if (o < OUTD) {
        float acc = bf[o];
        #pragma unroll
        for (int h = 0; h < DIM; h++)
            acc = fmaf(g_pool[h] * (1.f / NN), Wf[h * OUTD + o], acc);
        out[o] = acc;
    }
}

extern "C" void kernel_launch(void* const* d_in, const int* in_sizes, int n_in,
                              void* d_out, int out_size)
{
    const float* x     = (const float*)d_in[0];
    const int*   adj   = (const int*)  d_in[1];
    const float* W1    = (const float*)d_in[2];
    const float* b1    = (const float*)d_in[3];
    const float* gamma = (const float*)d_in[4];
    const float* beta  = (const float*)d_in[5];
    const float* W2    = (const float*)d_in[6];
    const float* b2    = (const float*)d_in[7];
    const float* Wf    = (const float*)d_in[8];
    const float* bf    = (const float*)d_in[9];
    float* out = (float*)d_out;

    k_zero<<<1, 64>>>();
    k_agg<<<NN / 32, 256>>>(adj, x, W1, b1);
    k_mlp2<<<NN / 256, 256>>>(gamma, beta, W2, b2);
    k_final<<<1, 32>>>(Wf, bf, out);
}

// round 2
// speedup vs baseline: 1.4128x; 1.4128x over previous
#include <cuda_runtime.h>
#include <cuda_bf16.h>

#define NN 16384
#define DIM 32
#define OUTD 16
#define BN_EPS 1e-5f

// Scratch (allocation-free rule: __device__ globals)
__device__ float g_agg[(size_t)NN * DIM];   // adj^T @ x (2 MB)
__device__ float g_h1[(size_t)NN * DIM];    // pre-BN hidden (2 MB)
__device__ float g_stats[2 * DIM];          // [0:32) sum, [32:64) sumsq of h1 cols
__device__ float g_pool[DIM];               // pooled sum of h2 cols

// ---------------------------------------------------------------------------
// K0: zero agg + accumulators (must run every graph replay).
// Grid 512 x 256: exactly 131072 float4 = 524288 floats of g_agg.
// ---------------------------------------------------------------------------
__global__ __launch_bounds__(256) void k_zero() {
    unsigned t = blockIdx.x * 256u + threadIdx.x;
    ((float4*)g_agg)[t] = make_float4(0.f, 0.f, 0.f, 0.f);
    if (blockIdx.x == 0) {
        if (threadIdx.x < 2 * DIM) g_stats[threadIdx.x] = 0.f;
        if (threadIdx.x < DIM)     g_pool[threadIdx.x]  = 0.f;
    }
}

// ---------------------------------------------------------------------------
// K1: flat streaming scan of adj (as int4) + atomic scatter of nonzeros.
// Grid 1024 x 256 = 262144 threads; 67,108,864 int4 total -> 256 per thread,
// processed as 32 batches of 8 (8 LDG.128 in flight per thread per batch).
// element (j, c): agg[c] += adj[j][c] * x[j]
// ---------------------------------------------------------------------------
__global__ __launch_bounds__(256) void k_scan(const int4* __restrict__ A,
                                              const float* __restrict__ x)
{
    const unsigned T    = gridDim.x * blockDim.x;          // 262144
    const unsigned base = blockIdx.x * blockDim.x + threadIdx.x;

    for (int it = 0; it < 32; ++it) {
        const unsigned f0 = base + (unsigned)it * (T * 8u);
        int4 v[8];
        #pragma unroll
        for (int u = 0; u < 8; ++u) v[u] = A[f0 + (unsigned)u * T];

        // OR-reduce 32 words -> one branch (LOP3 tree, ~16 ops)
        int r = 0;
        #pragma unroll
        for (int u = 0; u < 8; ++u)
            r |= (v[u].x | v[u].y) | (v[u].z | v[u].w);

        if (r) {                                           // ~6% of batches
            #pragma unroll
            for (int u = 0; u < 8; ++u) {
                if ((v[u].x | v[u].y) | (v[u].z | v[u].w)) {
                    const unsigned f  = f0 + (unsigned)u * T;
                    const unsigned j  = f >> 12;           // 4096 int4 per row
                    const unsigned c4 = (f & 4095u) << 2;  // first of 4 columns
                    const float* xr = x + ((size_t)j << 5);
                    const int e[4] = {v[u].x, v[u].y, v[u].z, v[u].w};
                    #pragma unroll
                    for (int q = 0; q < 4; ++q) {
                        if (e[q]) {
                            const float s = (float)e[q];
                            float* ar = g_agg + ((size_t)(c4 + q) << 5);
                            #pragma unroll
                            for (int d = 0; d < DIM; d += 4) {
                                float4 xv = *(const float4*)(xr + d);
                                atomicAdd(ar + d + 0, s * xv.x);
                                atomicAdd(ar + d + 1, s * xv.y);
                                atomicAdd(ar + d + 2, s * xv.z);
                                atomicAdd(ar + d + 3, s * xv.w);
                            }
                        }
                    }
                }
            }
        }
    }
}

// ---------------------------------------------------------------------------
// K1b: h1 = (x + agg) @ W1 + b1, plus BN partial sums.
// Grid 64 x 256: one node per thread; staged through padded shared.
// ---------------------------------------------------------------------------
__global__ __launch_bounds__(256) void k_h1(const float* __restrict__ x,
                                            const float* __restrict__ W1,
                                            const float* __restrict__ b1)
{
    __shared__ float sh[256 * 33];       // padded (x+agg) staging, reused for out
    __shared__ float sW[DIM * DIM];      // W1 transposed: [o][d]
    __shared__ float sB1[DIM];
    __shared__ float sSum[DIM], sSq[DIM];

    const int tid  = threadIdx.x;
    const int base = blockIdx.x * 256;

    if (tid < DIM) {
        sB1[tid]  = b1[tid];
        sSum[tid] = 0.f;
        sSq[tid]  = 0.f;
    }
    for (int k = tid; k < DIM * DIM; k += 256) {
        int d = k >> 5, o = k & 31;
        sW[o * DIM + d] = W1[k];
    }
    const float* xs = x     + (size_t)base * DIM;
    const float* as = g_agg + (size_t)base * DIM;
    for (int k = tid; k < 256 * DIM; k += 256)
        sh[(k >> 5) * 33 + (k & 31)] = xs[k] + as[k];
    __syncthreads();

    float v[DIM];
    {
        const float* hrow = sh + tid * 33;
        #pragma unroll
        for (int d = 0; d < DIM; ++d) v[d] = hrow[d];
    }
    float h[DIM];
    #pragma unroll
    for (int o = 0; o < DIM; ++o) {
        float acc = sB1[o];
        const float* wr = sW + o * DIM;
        #pragma unroll
        for (int d = 0; d < DIM; ++d) acc = fmaf(v[d], wr[d], acc);
        h[o] = acc;
    }
    __syncthreads();                     // done reading sh inputs

    // stage outputs for coalesced store
    {
        float* orow = sh + tid * 33;
        #pragma unroll
        for (int o = 0; o < DIM; ++o) orow[o] = h[o];
    }

    // BN partial sums: warp-reduce each output dim, shared-atomic per warp
    const int lane = tid & 31;
    #pragma unroll
    for (int o = 0; o < DIM; ++o) {
        float s = h[o], q = h[o] * h[o];
        #pragma unroll
        for (int off = 16; off > 0; off >>= 1) {
            s += __shfl_down_sync(0xFFFFFFFFu, s, off);
            q += __shfl_down_sync(0xFFFFFFFFu, q, off);
        }
        if (lane == 0) { atomicAdd(&sSum[o], s); atomicAdd(&sSq[o], q); }
    }
    __syncthreads();

    float* dst = g_h1 + (size_t)base * DIM;
    for (int k = tid; k < 256 * DIM; k += 256)
        dst[k] = sh[(k >> 5) * 33 + (k & 31)];
    if (tid < DIM) {
        atomicAdd(&g_stats[tid],       sSum[tid]);
        atomicAdd(&g_stats[DIM + tid], sSq[tid]);
    }
}

// ---------------------------------------------------------------------------
// K2: BN(train stats) + ReLU + @W2 + ReLU + mean-pool partials.
// ---------------------------------------------------------------------------
__global__ __launch_bounds__(256) void k_mlp2(
    const float* __restrict__ gamma,
    const float* __restrict__ beta,
    const float* __restrict__ W2,
    const float* __restrict__ b2)
{
    __shared__ float sh[256 * 33];
    __shared__ float sW2T[DIM * DIM];
    __shared__ float sScale[DIM], sShift[DIM], sB2[DIM], sPool[DIM];

    const int tid  = threadIdx.x;
    const int base = blockIdx.x * 256;

    if (tid < DIM) {
        float mean = g_stats[tid] * (1.f / NN);
        float var  = g_stats[DIM + tid] * (1.f / NN) - mean * mean;
        float sc   = gamma[tid] * rsqrtf(var + BN_EPS);
        sScale[tid] = sc;
        sShift[tid] = beta[tid] - mean * sc;
        sB2[tid]    = b2[tid];
        sPool[tid]  = 0.f;
    }
    for (int k = tid; k < DIM * DIM; k += 256) {
        int d = k >> 5, o = k & 31;
        sW2T[o * DIM + d] = W2[k];
    }
    const float* src = g_h1 + (size_t)base * DIM;
    for (int k = tid; k < 256 * DIM; k += 256)
        sh[(k >> 5) * 33 + (k & 31)] = src[k];
    __syncthreads();

    const float* hrow = sh + tid * 33;
    float v[DIM];
    #pragma unroll
    for (int d = 0; d < DIM; ++d)
        v[d] = fmaxf(fmaf(hrow[d], sScale[d], sShift[d]), 0.f);

    const int lane = tid & 31;
    #pragma unroll
    for (int o = 0; o < DIM; ++o) {
        float h2 = sB2[o];
        const float* wr = sW2T + o * DIM;
        #pragma unroll
        for (int d = 0; d < DIM; ++d) h2 = fmaf(v[d], wr[d], h2);
        h2 = fmaxf(h2, 0.f);
        #pragma unroll
        for (int off = 16; off > 0; off >>= 1)
            h2 += __shfl_down_sync(0xFFFFFFFFu, h2, off);
        if (lane == 0) atomicAdd(&sPool[o], h2);
    }
    __syncthreads();
    if (tid < DIM) atomicAdd(&g_pool[tid], sPool[tid]);
}

// ---------------------------------------------------------------------------
// K3: out = (pool/N) @ Wf + bf   (1 x 16)
// ---------------------------------------------------------------------------
__global__ void k_final(const float* __restrict__ Wf,
                        const float* __restrict__ bf,
                        float* __restrict__ out)
{
    int o = threadIdx.x;
    if (o < OUTD) {
        float acc = bf[o];
        #pragma unroll
        for (int h = 0; h < DIM; ++h)
            acc = fmaf(g_pool[h] * (1.f / NN), Wf[h * OUTD + o], acc);
        out[o] = acc;
    }
}

extern "C" void kernel_launch(void* const* d_in, const int* in_sizes, int n_in,
                              void* d_out, int out_size)
{
    const float* x     = (const float*)d_in[0];
    const int*   adj   = (const int*)  d_in[1];
    const float* W1    = (const float*)d_in[2];
    const float* b1    = (const float*)d_in[3];
    const float* gamma = (const float*)d_in[4];
    const float* beta  = (const float*)d_in[5];
    const float* W2    = (const float*)d_in[6];
    const float* b2    = (const float*)d_in[7];
    const float* Wf    = (const float*)d_in[8];
    const float* bf    = (const float*)d_in[9];
    float* out = (float*)d_out;

    k_zero<<<512, 256>>>();
    k_scan<<<1024, 256>>>((const int4*)adj, x);
    k_h1<<<64, 256>>>(x, W1, b1);
    k_mlp2<<<64, 256>>>(gamma, beta, W2, b2);
    k_final<<<1, 32>>>(Wf, bf, out);
}

// round 3
// speedup vs baseline: 1.9779x; 1.4000x over previous
#include <cuda_runtime.h>
#include <cuda_bf16.h>

#define NN 16384
#define DIM 32
#define OUTD 16
#define BN_EPS 1e-5f

#define SCAN_GRID    592          // 4 CTAs per SM exactly (148*4)
#define SCAN_THREADS 128
#define DEPTH        5
#define STAGE_INT4   512          // 8 KB per stage
#define STAGE_BYTES  8192
#define TOTAL_STAGES 131072       // 2^26 int4 / 512

// Scratch (allocation-free rule: __device__ globals)
__device__ float    g_agg[(size_t)NN * DIM];   // adj^T @ x (2 MB)
__device__ float    g_h1[(size_t)NN * DIM];    // pre-BN hidden (2 MB)
__device__ float    g_stats[2 * DIM];          // sum / sumsq of h1 cols
__device__ float    g_pool[DIM];               // pooled sum of h2 cols
__device__ unsigned g_done;                    // completion counter for fused FC

// ---------------- PTX helpers (self-contained) ----------------
__device__ __forceinline__ unsigned smem_u32(const void* p) {
    return (unsigned)__cvta_generic_to_shared(p);
}
__device__ __forceinline__ void mbar_init(unsigned a, unsigned cnt) {
    asm volatile("mbarrier.init.shared.b64 [%0], %1;" :: "r"(a), "r"(cnt) : "memory");
}
__device__ __forceinline__ void mbar_expect_tx(unsigned a, unsigned bytes) {
    asm volatile("mbarrier.arrive.expect_tx.shared.b64 _, [%0], %1;"
                 :: "r"(a), "r"(bytes) : "memory");
}
__device__ __forceinline__ void mbar_arrive(unsigned a) {
    asm volatile("mbarrier.arrive.shared.b64 _, [%0];" :: "r"(a) : "memory");
}
__device__ __forceinline__ void mbar_wait(unsigned a, unsigned phase) {
    asm volatile(
        "{\n\t.reg .pred P;\n\t"
        "WL_%=:\n\t"
        "mbarrier.try_wait.parity.acquire.cta.shared::cta.b64 P, [%0], %1, 0x989680;\n\t"
        "@P bra.uni WD_%=;\n\t"
        "bra.uni WL_%=;\n\t"
        "WD_%=:\n\t}"
        :: "r"(a), "r"(phase) : "memory");
}
__device__ __forceinline__ void bulk_g2s(unsigned dst, const void* src,
                                         unsigned bytes, unsigned mbar) {
    asm volatile(
        "cp.async.bulk.shared::cluster.global.mbarrier::complete_tx::bytes "
        "[%0], [%1], %2, [%3];"
        :: "r"(dst), "l"(src), "r"(bytes), "r"(mbar) : "memory");
}

// ---------------------------------------------------------------------------
// K0: zero agg + accumulators (must run every graph replay)
// ---------------------------------------------------------------------------
__global__ __launch_bounds__(256) void k_zero() {
    unsigned t = blockIdx.x * 256u + threadIdx.x;
    ((float4*)g_agg)[t] = make_float4(0.f, 0.f, 0.f, 0.f);
    if (blockIdx.x == 0) {
        if (threadIdx.x < 2 * DIM) g_stats[threadIdx.x] = 0.f;
        if (threadIdx.x < DIM)     g_pool[threadIdx.x]  = 0.f;
        if (threadIdx.x == 0)      g_done = 0u;
    }
}

// ---------------------------------------------------------------------------
// K1: TMA-pipelined streaming scan of adj + atomic scatter of nonzeros.
// 592 CTAs x 128 threads; 5-stage x 8KB cp.async.bulk ring per CTA.
// Stage s (global) covers flat int4 range [s*512, (s+1)*512);
// CTA b owns stages b, b+592, b+1184, ...
// ---------------------------------------------------------------------------
__global__ __launch_bounds__(SCAN_THREADS) void k_scan(
    const char*  __restrict__ Ag,
    const float* __restrict__ x)
{
    __shared__ __align__(128) int4 buf[DEPTH][STAGE_INT4];
    __shared__ __align__(8) unsigned long long mbar[2 * DEPTH]; // [full,empty] x DEPTH

    const int tid = threadIdx.x;
    const int bid = blockIdx.x;

    unsigned mb0 = smem_u32(mbar);
    #define FULL(d)  (mb0 + (unsigned)(d) * 16u)
    #define EMPTY(d) (mb0 + (unsigned)(d) * 16u + 8u)

    if (tid == 0) {
        #pragma unroll
        for (int d = 0; d < DEPTH; ++d) {
            mbar_init(FULL(d), 1);
            mbar_init(EMPTY(d), SCAN_THREADS);
        }
    }
    __syncthreads();

    const int cnt = (TOTAL_STAGES - bid + SCAN_GRID - 1) / SCAN_GRID;  // 221 or 222

    // prologue: fill the ring
    if (tid == 0) {
        int pre = cnt < DEPTH ? cnt : DEPTH;
        for (int k = 0; k < pre; ++k) {
            int s = bid + k * SCAN_GRID;
            mbar_expect_tx(FULL(k), STAGE_BYTES);
            bulk_g2s(smem_u32(buf[k]), Ag + (size_t)s * STAGE_BYTES,
                     STAGE_BYTES, FULL(k));
        }
    }

    int slot = 0;
    unsigned ph = 0;                       // shared phase for full & empty waits
    for (int k = 0; k < cnt; ++k) {
        mbar_wait(FULL(slot), ph);

        const unsigned s = (unsigned)(bid + k * SCAN_GRID);
        #pragma unroll
        for (int u = 0; u < 4; ++u) {
            const int idx = tid + u * SCAN_THREADS;
            int4 v = buf[slot][idx];
            if ((v.x | v.y) | (v.z | v.w)) {
                const unsigned flat = s * STAGE_INT4 + (unsigned)idx;
                const unsigned j    = flat >> 12;            // 4096 int4 per adj row
                const unsigned c4   = (flat & 4095u) << 2;   // first of 4 columns
                const float* xr = x + ((size_t)j << 5);
                const int e[4] = {v.x, v.y, v.z, v.w};
                #pragma unroll
                for (int q = 0; q < 4; ++q) {
                    if (e[q]) {
                        const float s2 = (float)e[q];
                        float* ar = g_agg + ((size_t)(c4 + q) << 5);
                        #pragma unroll
                        for (int d = 0; d < DIM; d += 4) {
                            float4 xv = *(const float4*)(xr + d);
                            atomicAdd(ar + d + 0, s2 * xv.x);
                            atomicAdd(ar + d + 1, s2 * xv.y);
                            atomicAdd(ar + d + 2, s2 * xv.z);
                            atomicAdd(ar + d + 3, s2 * xv.w);
                        }
                    }
                }
            }
        }

        mbar_arrive(EMPTY(slot));
        if (tid == 0 && k + DEPTH < cnt) {
            mbar_wait(EMPTY(slot), ph);    // all 128 consumed this slot
            int s2 = bid + (k + DEPTH) * SCAN_GRID;
            mbar_expect_tx(FULL(slot), STAGE_BYTES);
            bulk_g2s(smem_u32(buf[slot]), Ag + (size_t)s2 * STAGE_BYTES,
                     STAGE_BYTES, FULL(slot));
        }
        if (++slot == DEPTH) { slot = 0; ph ^= 1u; }
    }
    #undef FULL
    #undef EMPTY
}

// ---------------------------------------------------------------------------
// K1b: h1 = (x + agg) @ W1 + b1, plus BN partial sums.
// Grid 128 x 128: one node per thread, staged through padded shared.
// ---------------------------------------------------------------------------
__global__ __launch_bounds__(128) void k_h1(const float* __restrict__ x,
                                            const float* __restrict__ W1,
                                            const float* __restrict__ b1)
{
    __shared__ float sh[128 * 33];
    __shared__ float sW[DIM * DIM];      // W1 transposed: [o][d]
    __shared__ float sB1[DIM], sSum[DIM], sSq[DIM];

    const int tid  = threadIdx.x;
    const int base = blockIdx.x * 128;

    if (tid < DIM) { sB1[tid] = b1[tid]; sSum[tid] = 0.f; sSq[tid] = 0.f; }
    for (int k = tid; k < DIM * DIM; k += 128) {
        int d = k >> 5, o = k & 31;
        sW[o * DIM + d] = W1[k];
    }
    const float* xs = x     + (size_t)base * DIM;
    const float* as = g_agg + (size_t)base * DIM;
    for (int k = tid; k < 128 * DIM; k += 128)
        sh[(k >> 5) * 33 + (k & 31)] = xs[k] + as[k];
    __syncthreads();

    float v[DIM];
    {
        const float* hr = sh + tid * 33;
        #pragma unroll
        for (int d = 0; d < DIM; ++d) v[d] = hr[d];
    }
    float h[DIM];
    #pragma unroll
    for (int o = 0; o < DIM; ++o) {
        float acc = sB1[o];
        const float* wr = sW + o * DIM;
        #pragma unroll
        for (int d = 0; d < DIM; ++d) acc = fmaf(v[d], wr[d], acc);
        h[o] = acc;
    }
    __syncthreads();                     // done reading sh inputs

    {
        float* orow = sh + tid * 33;
        #pragma unroll
        for (int o = 0; o < DIM; ++o) orow[o] = h[o];
    }

    const int lane = tid & 31;
    #pragma unroll
    for (int o = 0; o < DIM; ++o) {
        float s = h[o], q = h[o] * h[o];
        #pragma unroll
        for (int off = 16; off > 0; off >>= 1) {
            s += __shfl_down_sync(0xFFFFFFFFu, s, off);
            q += __shfl_down_sync(0xFFFFFFFFu, q, off);
        }
        if (lane == 0) { atomicAdd(&sSum[o], s); atomicAdd(&sSq[o], q); }
    }
    __syncthreads();

    float* dst = g_h1 + (size_t)base * DIM;
    for (int k = tid; k < 128 * DIM; k += 128)
        dst[k] = sh[(k >> 5) * 33 + (k & 31)];
    if (tid < DIM) {
        atomicAdd(&g_stats[tid],       sSum[tid]);
        atomicAdd(&g_stats[DIM + tid], sSq[tid]);
    }
}

// ---------------------------------------------------------------------------
// K2: BN(train stats) + ReLU + @W2 + ReLU + mean-pool, with the final
// 1x16 FC fused into the last block to finish (completion counter).
// ---------------------------------------------------------------------------
__global__ __launch_bounds__(128) void k_mlp2(
    const float* __restrict__ gamma,
    const float* __restrict__ beta,
    const float* __restrict__ W2,
    const float* __restrict__ b2,
    const float* __restrict__ Wf,
    const float* __restrict__ bf,
    float*       __restrict__ out)
{
    __shared__ float sh[128 * 33];
    __shared__ float sW2T[DIM * DIM];
    __shared__ float sScale[DIM], sShift[DIM], sB2[DIM], sPool[DIM];
    __shared__ int   sLast;

    const int tid  = threadIdx.x;
    const int base = blockIdx.x * 128;

    if (tid < DIM) {
        float mean = g_stats[tid] * (1.f / NN);
        float var  = g_stats[DIM + tid] * (1.f / NN) - mean * mean;
        float sc   = gamma[tid] * rsqrtf(var + BN_EPS);
        sScale[tid] = sc;
        sShift[tid] = beta[tid] - mean * sc;
        sB2[tid]    = b2[tid];
        sPool[tid]  = 0.f;
    }
    for (int k = tid; k < DIM * DIM; k += 128) {
        int d = k >> 5, o = k & 31;
        sW2T[o * DIM + d] = W2[k];
    }
    const float* src = g_h1 + (size_t)base * DIM;
    for (int k = tid; k < 128 * DIM; k += 128)
        sh[(k >> 5) * 33 + (k & 31)] = src[k];
    __syncthreads();

    const float* hr = sh + tid * 33;
    float v[DIM];
    #pragma unroll
    for (int d = 0; d < DIM; ++d)
        v[d] = fmaxf(fmaf(hr[d], sScale[d], sShift[d]), 0.f);

    const int lane = tid & 31;
    #pragma unroll
    for (int o = 0; o < DIM; ++o) {
        float h2 = sB2[o];
        const float* wr = sW2T + o * DIM;
        #pragma unroll
        for (int d = 0; d < DIM; ++d) h2 = fmaf(v[d], wr[d], h2);
        h2 = fmaxf(h2, 0.f);
        #pragma unroll
        for (int off = 16; off > 0; off >>= 1)
            h2 += __shfl_down_sync(0xFFFFFFFFu, h2, off);
        if (lane == 0) atomicAdd(&sPool[o], h2);
    }
    __syncthreads();
    if (tid < DIM) atomicAdd(&g_pool[tid], sPool[tid]);

    // ---- fused final FC: last block to finish computes out = pool/N @ Wf + bf
    __threadfence();
    __syncthreads();
    if (tid == 0) {
        unsigned done = atomicAdd(&g_done, 1u);
        sLast = (done == gridDim.x - 1) ? 1 : 0;
    }
    __syncthreads();
    if (sLast) {
        __threadfence();                 // acquire other blocks' pool adds
        if (tid < OUTD) {
            float acc = bf[tid];
            #pragma unroll
            for (int h = 0; h < DIM; ++h)
                acc = fmaf(g_pool[h] * (1.f / NN), Wf[h * OUTD + tid], acc);
            out[tid] = acc;
        }
        if (tid == 0) g_done = 0u;       // reset for next graph replay
    }
}

extern "C" void kernel_launch(void* const* d_in, const int* in_sizes, int n_in,
                              void* d_out, int out_size)
{
    const float* x     = (const float*)d_in[0];
    const int*   adj   = (const int*)  d_in[1];
    const float* W1    = (const float*)d_in[2];
    const float* b1    = (const float*)d_in[3];
    const float* gamma = (const float*)d_in[4];
    const float* beta  = (const float*)d_in[5];
    const float* W2    = (const float*)d_in[6];
    const float* b2    = (const float*)d_in[7];
    const float* Wf    = (const float*)d_in[8];
    const float* bf    = (const float*)d_in[9];
    float* out = (float*)d_out;

    k_zero<<<512, 256>>>();
    k_scan<<<SCAN_GRID, SCAN_THREADS>>>((const char*)adj, x);
    k_h1<<<NN / 128, 128>>>(x, W1, b1);
    k_mlp2<<<NN / 128, 128>>>(gamma, beta, W2, b2, Wf, bf, out);
}

// round 4
// speedup vs baseline: 2.3041x; 1.1649x over previous
#include <cuda_runtime.h>
#include <cuda_bf16.h>

#define NN 16384
#define DIM 32
#define OUTD 16
#define BN_EPS 1e-5f

#define SCAN_GRID    592          // 4 CTAs per SM exactly (148*4)
#define SCAN_THREADS 128
#define DEPTH        5
#define STAGE_INT4   512          // 8 KB per stage
#define STAGE_BYTES  8192
#define TOTAL_STAGES 131072       // 2^26 int4 / 512

#define TAIL_GRID    128          // <= 148 SMs: all blocks co-resident (barrier-safe)
#define TAIL_THREADS 128

// Scratch (__device__ globals start zero; tail kernel re-zeroes each call)
__device__ float    g_agg[(size_t)NN * DIM];   // adj^T @ x (2 MB)
__device__ float    g_stats[2 * DIM];          // sum / sumsq of h1 cols
__device__ float    g_pool[DIM];               // pooled sum of h2 cols
__device__ unsigned g_arrive;                  // device-barrier counter
__device__ unsigned g_done;                    // completion counter

// ---------------- PTX helpers ----------------
__device__ __forceinline__ unsigned smem_u32(const void* p) {
    return (unsigned)__cvta_generic_to_shared(p);
}
__device__ __forceinline__ void mbar_init(unsigned a, unsigned cnt) {
    asm volatile("mbarrier.init.shared.b64 [%0], %1;" :: "r"(a), "r"(cnt) : "memory");
}
__device__ __forceinline__ void mbar_expect_tx(unsigned a, unsigned bytes) {
    asm volatile("mbarrier.arrive.expect_tx.shared.b64 _, [%0], %1;"
                 :: "r"(a), "r"(bytes) : "memory");
}
__device__ __forceinline__ void mbar_arrive(unsigned a) {
    asm volatile("mbarrier.arrive.shared.b64 _, [%0];" :: "r"(a) : "memory");
}
__device__ __forceinline__ void mbar_wait(unsigned a, unsigned phase) {
    asm volatile(
        "{\n\t.reg .pred P;\n\t"
        "WL_%=:\n\t"
        "mbarrier.try_wait.parity.acquire.cta.shared::cta.b64 P, [%0], %1, 0x989680;\n\t"
        "@P bra.uni WD_%=;\n\t"
        "bra.uni WL_%=;\n\t"
        "WD_%=:\n\t}"
        :: "r"(a), "r"(phase) : "memory");
}
__device__ __forceinline__ void bulk_g2s(unsigned dst, const void* src,
                                         unsigned bytes, unsigned mbar) {
    asm volatile(
        "cp.async.bulk.shared::cluster.global.mbarrier::complete_tx::bytes "
        "[%0], [%1], %2, [%3];"
        :: "r"(dst), "l"(src), "r"(bytes), "r"(mbar) : "memory");
}
__device__ __forceinline__ void red_add_v4(float* p, float a, float b, float c, float d) {
    asm volatile("red.global.add.v4.f32 [%0], {%1, %2, %3, %4};"
                 :: "l"(p), "f"(a), "f"(b), "f"(c), "f"(d) : "memory");
}

// ---------------------------------------------------------------------------
// K1: TMA-pipelined streaming scan of adj + v4-atomic scatter of nonzeros.
// ---------------------------------------------------------------------------
__global__ __launch_bounds__(SCAN_THREADS) void k_scan(
    const char*  __restrict__ Ag,
    const float* __restrict__ x)
{
    __shared__ __align__(128) int4 buf[DEPTH][STAGE_INT4];
    __shared__ __align__(8) unsigned long long mbar[2 * DEPTH];

    const int tid = threadIdx.x;
    const int bid = blockIdx.x;

    unsigned mb0 = smem_u32(mbar);
    #define FULL(d)  (mb0 + (unsigned)(d) * 16u)
    #define EMPTY(d) (mb0 + (unsigned)(d) * 16u + 8u)

    if (tid == 0) {
        #pragma unroll
        for (int d = 0; d < DEPTH; ++d) {
            mbar_init(FULL(d), 1);
            mbar_init(EMPTY(d), SCAN_THREADS);
        }
    }
    __syncthreads();

    const int cnt = (TOTAL_STAGES - bid + SCAN_GRID - 1) / SCAN_GRID;

    if (tid == 0) {
        int pre = cnt < DEPTH ? cnt : DEPTH;
        for (int k = 0; k < pre; ++k) {
            int s = bid + k * SCAN_GRID;
            mbar_expect_tx(FULL(k), STAGE_BYTES);
            bulk_g2s(smem_u32(buf[k]), Ag + (size_t)s * STAGE_BYTES,
                     STAGE_BYTES, FULL(k));
        }
    }

    int slot = 0;
    unsigned ph = 0;
    for (int k = 0; k < cnt; ++k) {
        mbar_wait(FULL(slot), ph);

        const unsigned s = (unsigned)(bid + k * SCAN_GRID);
        #pragma unroll
        for (int u = 0; u < 4; ++u) {
            const int idx = tid + u * SCAN_THREADS;
            int4 v = buf[slot][idx];
            if ((v.x | v.y) | (v.z | v.w)) {
                const unsigned flat = s * STAGE_INT4 + (unsigned)idx;
                const unsigned j    = flat >> 12;            // 4096 int4 per adj row
                const unsigned c4   = (flat & 4095u) << 2;   // first of 4 columns
                const float* xr = x + ((size_t)j << 5);
                const int e[4] = {v.x, v.y, v.z, v.w};
                #pragma unroll
                for (int q = 0; q < 4; ++q) {
                    if (e[q]) {
                        const float sc = (float)e[q];
                        float* ar = g_agg + ((size_t)(c4 + q) << 5);
                        #pragma unroll
                        for (int d = 0; d < DIM; d += 4) {
                            float4 xv = __ldg((const float4*)(xr + d));
                            red_add_v4(ar + d, sc * xv.x, sc * xv.y,
                                               sc * xv.z, sc * xv.w);
                        }
                    }
                }
            }
        }

        mbar_arrive(EMPTY(slot));
        if (tid == 0 && k + DEPTH < cnt) {
            mbar_wait(EMPTY(slot), ph);
            int s2 = bid + (k + DEPTH) * SCAN_GRID;
            mbar_expect_tx(FULL(slot), STAGE_BYTES);
            bulk_g2s(smem_u32(buf[slot]), Ag + (size_t)s2 * STAGE_BYTES,
                     STAGE_BYTES, FULL(slot));
        }
        if (++slot == DEPTH) { slot = 0; ph ^= 1u; }
    }
    #undef FULL
    #undef EMPTY
}

// ---------------------------------------------------------------------------
// K2 (fused tail): h1 = (x+agg)@W1+b1 -> BN stats -> device barrier ->
// BN+ReLU -> @W2+ReLU -> mean pool -> final FC (last block) -> state cleanup.
// 128 blocks x 128 threads; one node per thread; h1 register-resident.
// ---------------------------------------------------------------------------
__global__ __launch_bounds__(TAIL_THREADS) void k_tail(
    const float* __restrict__ x,
    const float* __restrict__ W1,
    const float* __restrict__ b1,
    const float* __restrict__ gamma,
    const float* __restrict__ beta,
    const float* __restrict__ W2,
    const float* __restrict__ b2,
    const float* __restrict__ Wf,
    const float* __restrict__ bf,
    float*       __restrict__ out)
{
    __shared__ float sW1[DIM * DIM];     // W1 transposed: [o][d]
    __shared__ float sW2[DIM * DIM];     // W2 transposed: [o][d]
    __shared__ float sB1[DIM], sSum[DIM], sSq[DIM];
    __shared__ float sScale[DIM], sShift[DIM], sB2[DIM], sPool[DIM];
    __shared__ int   sLast;

    const int tid  = threadIdx.x;
    const int lane = tid & 31;
    const int node = blockIdx.x * TAIL_THREADS + tid;

    if (tid < DIM) {
        sB1[tid]  = b1[tid];
        sSum[tid] = 0.f; sSq[tid] = 0.f; sPool[tid] = 0.f;
    }
    for (int k = tid; k < DIM * DIM; k += TAIL_THREADS) {
        int d = k >> 5, o = k & 31;
        sW1[o * DIM + d] = W1[k];
        sW2[o * DIM + d] = W2[k];
    }

    // v = x[node] + agg[node]  (register-resident); zero agg for next replay
    float v[DIM];
    {
        const float4* xr = (const float4*)(x + ((size_t)node << 5));
        float4*       ar = (float4*)(g_agg + ((size_t)node << 5));
        #pragma unroll
        for (int q = 0; q < 8; ++q) {
            float4 a = xr[q], b = ar[q];
            v[4*q+0] = a.x + b.x; v[4*q+1] = a.y + b.y;
            v[4*q+2] = a.z + b.z; v[4*q+3] = a.w + b.w;
            ar[q] = make_float4(0.f, 0.f, 0.f, 0.f);
        }
    }
    __syncthreads();

    // h1 = v @ W1 + b1
    float h[DIM];
    #pragma unroll
    for (int o = 0; o < DIM; ++o) {
        float acc = sB1[o];
        const float* wr = sW1 + o * DIM;
        #pragma unroll
        for (int d = 0; d < DIM; ++d) acc = fmaf(v[d], wr[d], acc);
        h[o] = acc;
    }

    // BN partial sums -> g_stats
    #pragma unroll
    for (int o = 0; o < DIM; ++o) {
        float s = h[o], q = h[o] * h[o];
        #pragma unroll
        for (int off = 16; off > 0; off >>= 1) {
            s += __shfl_down_sync(0xFFFFFFFFu, s, off);
            q += __shfl_down_sync(0xFFFFFFFFu, q, off);
        }
        if (lane == 0) { atomicAdd(&sSum[o], s); atomicAdd(&sSq[o], q); }
    }
    __syncthreads();
    if (tid < DIM) {
        atomicAdd(&g_stats[tid],       sSum[tid]);
        atomicAdd(&g_stats[DIM + tid], sSq[tid]);
    }

    // ---- device-wide barrier (all 128 blocks co-resident) ----
    __threadfence();
    __syncthreads();
    if (tid == 0) {
        atomicAdd(&g_arrive, 1u);
        unsigned seen;
        do {
            asm volatile("ld.acquire.gpu.u32 %0, [%1];"
                         : "=r"(seen) : "l"(&g_arrive) : "memory");
        } while (seen < (unsigned)gridDim.x);
    }
    __syncthreads();

    // BN finalize
    if (tid < DIM) {
        float mean = g_stats[tid] * (1.f / NN);
        float var  = g_stats[DIM + tid] * (1.f / NN) - mean * mean;
        float sc   = gamma[tid] * rsqrtf(var + BN_EPS);
        sScale[tid] = sc;
        sShift[tid] = beta[tid] - mean * sc;
        sB2[tid]    = b2[tid];
    }
    __syncthreads();

    // BN + ReLU
    float r[DIM];
    #pragma unroll
    for (int o = 0; o < DIM; ++o)
        r[o] = fmaxf(fmaf(h[o], sScale[o], sShift[o]), 0.f);

    // h2 = relu(r @ W2 + b2), reduce into pool
    #pragma unroll
    for (int o = 0; o < DIM; ++o) {
        float h2 = sB2[o];
        const float* wr = sW2 + o * DIM;
        #pragma unroll
        for (int d = 0; d < DIM; ++d) h2 = fmaf(r[d], wr[d], h2);
        h2 = fmaxf(h2, 0.f);
        #pragma unroll
        for (int off = 16; off > 0; off >>= 1)
            h2 += __shfl_down_sync(0xFFFFFFFFu, h2, off);
        if (lane == 0) atomicAdd(&sPool[o], h2);
    }
    __syncthreads();
    if (tid < DIM) atomicAdd(&g_pool[tid], sPool[tid]);

    // ---- last block: final FC + state cleanup ----
    __threadfence();
    __syncthreads();
    if (tid == 0) {
        unsigned done = atomicAdd(&g_done, 1u);
        sLast = (done == gridDim.x - 1) ? 1 : 0;
    }
    __syncthreads();
    if (sLast) {
        __threadfence();
        if (tid < OUTD) {
            float acc = bf[tid];
            #pragma unroll
            for (int hh = 0; hh < DIM; ++hh)
                acc = fmaf(g_pool[hh] * (1.f / NN), Wf[hh * OUTD + tid], acc);
            out[tid] = acc;
        }
        if (tid < 2 * DIM) g_stats[tid] = 0.f;
        if (tid < DIM)     g_pool[tid]  = 0.f;
        if (tid == 0)      { g_arrive = 0u; g_done = 0u; }
    }
}

extern "C" void kernel_launch(void* const* d_in, const int* in_sizes, int n_in,
                              void* d_out, int out_size)
{
    const float* x     = (const float*)d_in[0];
    const int*   adj   = (const int*)  d_in[1];
    const float* W1    = (const float*)d_in[2];
    const float* b1    = (const float*)d_in[3];
    const float* gamma = (const float*)d_in[4];
    const float* beta  = (const float*)d_in[5];
    const float* W2    = (const float*)d_in[6];
    const float* b2    = (const float*)d_in[7];
    const float* Wf    = (const float*)d_in[8];
    const float* bf    = (const float*)d_in[9];
    float* out = (float*)d_out;

    k_scan<<<SCAN_GRID, SCAN_THREADS>>>((const char*)adj, x);
    k_tail<<<TAIL_GRID, TAIL_THREADS>>>(x, W1, b1, gamma, beta, W2, b2, Wf, bf, out);
}

// round 5
// speedup vs baseline: 2.6711x; 1.1593x over previous
#include <cuda_runtime.h>
#include <cuda_bf16.h>

#define NN 16384
#define DIM 32
#define OUTD 16
#define BN_EPS 1e-5f

#define SCAN_GRID    592          // 4 CTAs per SM exactly (148*4)
#define SCAN_THREADS 128
#define SCAN_WARPS   4
#define DEPTH        5
#define STAGE_INT4   512          // 8 KB per stage
#define STAGE_BYTES  8192
#define TOTAL_STAGES 131072       // 2^26 int4 / 512

#define TAIL_GRID    128
#define TAIL_THREADS 128

// Scratch (__device__ globals start zero; tail kernel re-zeroes each call)
__device__ float    g_agg[(size_t)NN * DIM];
__device__ float    g_stats[2 * DIM];
__device__ float    g_pool[DIM];
__device__ float    g_sink;
__device__ unsigned g_arrive;
__device__ unsigned g_done;

// ---------------- PTX helpers ----------------
__device__ __forceinline__ unsigned smem_u32(const void* p) {
    return (unsigned)__cvta_generic_to_shared(p);
}
__device__ __forceinline__ void mbar_init(unsigned a, unsigned cnt) {
    asm volatile("mbarrier.init.shared.b64 [%0], %1;" :: "r"(a), "r"(cnt) : "memory");
}
__device__ __forceinline__ void mbar_expect_tx(unsigned a, unsigned bytes) {
    asm volatile("mbarrier.arrive.expect_tx.shared.b64 _, [%0], %1;"
                 :: "r"(a), "r"(bytes) : "memory");
}
__device__ __forceinline__ void mbar_arrive(unsigned a) {
    asm volatile("mbarrier.arrive.shared.b64 _, [%0];" :: "r"(a) : "memory");
}
__device__ __forceinline__ void mbar_wait(unsigned a, unsigned phase) {
    asm volatile(
        "{\n\t.reg .pred P;\n\t"
        "WL_%=:\n\t"
        "mbarrier.try_wait.parity.acquire.cta.shared::cta.b64 P, [%0], %1, 0x989680;\n\t"
        "@P bra.uni WD_%=;\n\t"
        "bra.uni WL_%=;\n\t"
        "WD_%=:\n\t}"
        :: "r"(a), "r"(phase) : "memory");
}
__device__ __forceinline__ void bulk_g2s(unsigned dst, const void* src,
                                         unsigned bytes, unsigned mbar) {
    asm volatile(
        "cp.async.bulk.shared::cluster.global.mbarrier::complete_tx::bytes "
        "[%0], [%1], %2, [%3];"
        :: "r"(dst), "l"(src), "r"(bytes), "r"(mbar) : "memory");
}
__device__ __forceinline__ void red_add_v4(float* p, float a, float b, float c, float d) {
    asm volatile("red.global.add.v4.f32 [%0], {%1, %2, %3, %4};"
                 :: "l"(p), "f"(a), "f"(b), "f"(c), "f"(d) : "memory");
}

// ---------------------------------------------------------------------------
// K0 (k_pre): warm x into L2 (2 MB). Also shifts the launch pattern so
// ncu -s 5 -c 1 captures k_scan (launch #6 = replay-2 scan).
// ---------------------------------------------------------------------------
__global__ __launch_bounds__(256) void k_pre(const float4* __restrict__ x4) {
    const int t = blockIdx.x * 256 + threadIdx.x;        // 16384 threads
    float s = 0.f;
    #pragma unroll
    for (int u = 0; u < 8; ++u) {
        float4 v = x4[t + u * 16384];
        s += v.x + v.y + v.z + v.w;
    }
    if (s == 1.2345e30f) g_sink = s;                     // never true; keeps loads
}

// ---------------------------------------------------------------------------
// K1: TMA-pipelined streaming scan of adj + v4-atomic scatter of nonzeros.
// EMPTY barrier now counts WARPS (4), arrived by lane 0 after __syncwarp.
// ---------------------------------------------------------------------------
__global__ __launch_bounds__(SCAN_THREADS) void k_scan(
    const char*  __restrict__ Ag,
    const float* __restrict__ x)
{
    __shared__ __align__(128) int4 buf[DEPTH][STAGE_INT4];
    __shared__ __align__(8) unsigned long long mbar[2 * DEPTH];

    const int tid  = threadIdx.x;
    const int lane = tid & 31;
    const int bid  = blockIdx.x;

    unsigned mb0 = smem_u32(mbar);
    #define FULL(d)  (mb0 + (unsigned)(d) * 16u)
    #define EMPTY(d) (mb0 + (unsigned)(d) * 16u + 8u)

    if (tid == 0) {
        #pragma unroll
        for (int d = 0; d < DEPTH; ++d) {
            mbar_init(FULL(d), 1);
            mbar_init(EMPTY(d), SCAN_WARPS);
        }
    }
    __syncthreads();

    const int cnt = (TOTAL_STAGES - bid + SCAN_GRID - 1) / SCAN_GRID;

    if (tid == 0) {
        int pre = cnt < DEPTH ? cnt : DEPTH;
        for (int k = 0; k < pre; ++k) {
            int s = bid + k * SCAN_GRID;
            mbar_expect_tx(FULL(k), STAGE_BYTES);
            bulk_g2s(smem_u32(buf[k]), Ag + (size_t)s * STAGE_BYTES,
                     STAGE_BYTES, FULL(k));
        }
    }

    int slot = 0;
    unsigned ph = 0;
    for (int k = 0; k < cnt; ++k) {
        mbar_wait(FULL(slot), ph);

        const unsigned s = (unsigned)(bid + k * SCAN_GRID);
        #pragma unroll
        for (int u = 0; u < 4; ++u) {
            const int idx = tid + u * SCAN_THREADS;
            int4 v = buf[slot][idx];
            if ((v.x | v.y) | (v.z | v.w)) {
                const unsigned flat = s * STAGE_INT4 + (unsigned)idx;
                const unsigned j    = flat >> 12;            // 4096 int4 per adj row
                const unsigned c4   = (flat & 4095u) << 2;   // first of 4 columns
                const float* xr = x + ((size_t)j << 5);
                const int e[4] = {v.x, v.y, v.z, v.w};
                #pragma unroll
                for (int q = 0; q < 4; ++q) {
                    if (e[q]) {
                        const float sc = (float)e[q];
                        float* ar = g_agg + ((size_t)(c4 + q) << 5);
                        #pragma unroll
                        for (int d = 0; d < DIM; d += 4) {
                            float4 xv = __ldg((const float4*)(xr + d));
                            red_add_v4(ar + d, sc * xv.x, sc * xv.y,
                                               sc * xv.z, sc * xv.w);
                        }
                    }
                }
            }
        }

        __syncwarp();
        if (lane == 0) mbar_arrive(EMPTY(slot));          // 4 arrives, not 128

        if (tid == 0 && k + DEPTH < cnt) {
            mbar_wait(EMPTY(slot), ph);
            int s2 = bid + (k + DEPTH) * SCAN_GRID;
            mbar_expect_tx(FULL(slot), STAGE_BYTES);
            bulk_g2s(smem_u32(buf[slot]), Ag + (size_t)s2 * STAGE_BYTES,
                     STAGE_BYTES, FULL(slot));
        }
        if (++slot == DEPTH) { slot = 0; ph ^= 1u; }
    }
    #undef FULL
    #undef EMPTY
}

// ---------------------------------------------------------------------------
// K2 (fused tail): h1 -> BN stats -> device barrier -> BN+ReLU -> @W2+ReLU
// -> mean pool -> final FC (last block) -> state cleanup.
// ---------------------------------------------------------------------------
__global__ __launch_bounds__(TAIL_THREADS) void k_tail(
    const float* __restrict__ x,
    const float* __restrict__ W1,
    const float* __restrict__ b1,
    const float* __restrict__ gamma,
    const float* __restrict__ beta,
    const float* __restrict__ W2,
    const float* __restrict__ b2,
    const float* __restrict__ Wf,
    const float* __restrict__ bf,
    float*       __restrict__ out)
{
    __shared__ float sW1[DIM * DIM];
    __shared__ float sW2[DIM * DIM];
    __shared__ float sB1[DIM], sSum[DIM], sSq[DIM];
    __shared__ float sScale[DIM], sShift[DIM], sB2[DIM], sPool[DIM];
    __shared__ int   sLast;

    const int tid  = threadIdx.x;
    const int lane = tid & 31;
    const int node = blockIdx.x * TAIL_THREADS + tid;

    if (tid < DIM) {
        sB1[tid]  = b1[tid];
        sSum[tid] = 0.f; sSq[tid] = 0.f; sPool[tid] = 0.f;
    }
    for (int k = tid; k < DIM * DIM; k += TAIL_THREADS) {
        int d = k >> 5, o = k & 31;
        sW1[o * DIM + d] = W1[k];
        sW2[o * DIM + d] = W2[k];
    }

    float v[DIM];
    {
        const float4* xr = (const float4*)(x + ((size_t)node << 5));
        float4*       ar = (float4*)(g_agg + ((size_t)node << 5));
        #pragma unroll
        for (int q = 0; q < 8; ++q) {
            float4 a = xr[q], b = ar[q];
            v[4*q+0] = a.x + b.x; v[4*q+1] = a.y + b.y;
            v[4*q+2] = a.z + b.z; v[4*q+3] = a.w + b.w;
            ar[q] = make_float4(0.f, 0.f, 0.f, 0.f);
        }
    }
    __syncthreads();

    float h[DIM];
    #pragma unroll
    for (int o = 0; o < DIM; ++o) {
        float acc = sB1[o];
        const float* wr = sW1 + o * DIM;
        #pragma unroll
        for (int d = 0; d < DIM; ++d) acc = fmaf(v[d], wr[d], acc);
        h[o] = acc;
    }

    #pragma unroll
    for (int o = 0; o < DIM; ++o) {
        float s = h[o], q = h[o] * h[o];
        #pragma unroll
        for (int off = 16; off > 0; off >>= 1) {
            s += __shfl_down_sync(0xFFFFFFFFu, s, off);
            q += __shfl_down_sync(0xFFFFFFFFu, q, off);
        }
        if (lane == 0) { atomicAdd(&sSum[o], s); atomicAdd(&sSq[o], q); }
    }
    __syncthreads();
    if (tid < DIM) {
        atomicAdd(&g_stats[tid],       sSum[tid]);
        atomicAdd(&g_stats[DIM + tid], sSq[tid]);
    }

    // ---- device-wide barrier (all 128 blocks co-resident) ----
    __threadfence();
    __syncthreads();
    if (tid == 0) {
        atomicAdd(&g_arrive, 1u);
        unsigned seen;
        do {
            asm volatile("ld.acquire.gpu.u32 %0, [%1];"
                         : "=r"(seen) : "l"(&g_arrive) : "memory");
        } while (seen < (unsigned)gridDim.x);
    }
    __syncthreads();

    if (tid < DIM) {
        float mean = g_stats[tid] * (1.f / NN);
        float var  = g_stats[DIM + tid] * (1.f / NN) - mean * mean;
        float sc   = gamma[tid] * rsqrtf(var + BN_EPS);
        sScale[tid] = sc;
        sShift[tid] = beta[tid] - mean * sc;
        sB2[tid]    = b2[tid];
    }
    __syncthreads();

    float r[DIM];
    #pragma unroll
    for (int o = 0; o < DIM; ++o)
        r[o] = fmaxf(fmaf(h[o], sScale[o], sShift[o]), 0.f);

    #pragma unroll
    for (int o = 0; o < DIM; ++o) {
        float h2 = sB2[o];
        const float* wr = sW2 + o * DIM;
        #pragma unroll
        for (int d = 0; d < DIM; ++d) h2 = fmaf(r[d], wr[d], h2);
        h2 = fmaxf(h2, 0.f);
        #pragma unroll
        for (int off = 16; off > 0; off >>= 1)
            h2 += __shfl_down_sync(0xFFFFFFFFu, h2, off);
        if (lane == 0) atomicAdd(&sPool[o], h2);
    }
    __syncthreads();
    if (tid < DIM) atomicAdd(&g_pool[tid], sPool[tid]);

    __threadfence();
    __syncthreads();
    if (tid == 0) {
        unsigned done = atomicAdd(&g_done, 1u);
        sLast = (done == gridDim.x - 1) ? 1 : 0;
    }
    __syncthreads();
    if (sLast) {
        __threadfence();
        if (tid < OUTD) {
            float acc = bf[tid];
            #pragma unroll
            for (int hh = 0; hh < DIM; ++hh)
                acc = fmaf(g_pool[hh] * (1.f / NN), Wf[hh * OUTD + tid], acc);
            out[tid] = acc;
        }
        if (tid < 2 * DIM) g_stats[tid] = 0.f;
        if (tid < DIM)     g_pool[tid]  = 0.f;
        if (tid == 0)      { g_arrive = 0u; g_done = 0u; }
    }
}

extern "C" void kernel_launch(void* const* d_in, const int* in_sizes, int n_in,
                              void* d_out, int out_size)
{
    const float* x     = (const float*)d_in[0];
    const int*   adj   = (const int*)  d_in[1];
    const float* W1    = (const float*)d_in[2];
    const float* b1    = (const float*)d_in[3];
    const float* gamma = (const float*)d_in[4];
    const float* beta  = (const float*)d_in[5];
    const float* W2    = (const float*)d_in[6];
    const float* b2    = (const float*)d_in[7];
    const float* Wf    = (const float*)d_in[8];
    const float* bf    = (const float*)d_in[9];
    float* out = (float*)d_out;

    k_pre <<<64, 256>>>((const float4*)x);
    k_scan<<<SCAN_GRID, SCAN_THREADS>>>((const char*)adj, x);
    k_tail<<<TAIL_GRID, TAIL_THREADS>>>(x, W1, b1, gamma, beta, W2, b2, Wf, bf, out);
}